// round 6
// baseline (speedup 1.0000x reference)
#include <cuda_runtime.h>

#define HID   1024
#define SEQ   4096
#define GRID  64      // RNN persistent CTAs (<= SM count -> co-resident)
#define RTHR  256     // 8 warps; 2 rows per warp -> 16 rows per CTA
#define SENT  0x7fffffffu   // NaN bit pattern: tanhf never produces it

// Scratch (device globals; no allocation)
__device__ float    g_emb[(size_t)SEQ * HID];          // normalized embeddings
__device__ float    g_pre[(size_t)SEQ * HID];          // W_hi @ x_t + b
__device__ unsigned g_hbuf[(size_t)(SEQ + 1) * HID];   // h bits, sentinel-init

// ---------------------------------------------------------------------------
// Kernel 0: reset comm buffer rows 1..SEQ to sentinel (every replay)
// ---------------------------------------------------------------------------
__global__ void init_kernel() {
    size_t n = (size_t)SEQ * (HID / 4);
    uint4 s4 = make_uint4(SENT, SENT, SENT, SENT);
    uint4* p = (uint4*)(g_hbuf + HID);   // rows 1..SEQ
    for (size_t i = (size_t)blockIdx.x * blockDim.x + threadIdx.x; i < n;
         i += (size_t)gridDim.x * blockDim.x)
        p[i] = s4;
}

// ---------------------------------------------------------------------------
// Kernel A: embedding lookup + L2 normalize; out[0]=h0; g_hbuf row 0 = h0
// ---------------------------------------------------------------------------
__global__ void embed_kernel(const int* __restrict__ src,
                             const float* __restrict__ W,
                             const float* __restrict__ h0,
                             float* __restrict__ out) {
    int t   = blockIdx.x;
    int tid = threadIdx.x;

    const float4* row = (const float4*)(W + (size_t)src[t] * HID);
    float4 v = row[tid];                       // 256 * 4 = 1024 elements
    float  ss = v.x*v.x + v.y*v.y + v.z*v.z + v.w*v.w;

    #pragma unroll
    for (int o = 16; o > 0; o >>= 1)
        ss += __shfl_xor_sync(0xffffffffu, ss, o);

    __shared__ float warp_ss[8];
    __shared__ float s_scale;
    int w = tid >> 5, l = tid & 31;
    if (l == 0) warp_ss[w] = ss;
    __syncthreads();
    if (tid == 0) {
        float tot = 0.f;
        #pragma unroll
        for (int i = 0; i < 8; i++) tot += warp_ss[i];
        float n = fmaxf(sqrtf(tot), 1e-12f);
        s_scale = 1.0f / n;
    }
    __syncthreads();

    float sc = s_scale;
    float4 o4 = make_float4(v.x*sc, v.y*sc, v.z*sc, v.w*sc);
    ((float4*)g_emb)[(size_t)t * (HID/4) + tid] = o4;

    if (t == 0) {  // out row 0 = h0; comm buffer row 0 = h0 bits
        float4 h = ((const float4*)h0)[tid];
        ((float4*)out)[tid] = h;
        ((uint4*)g_hbuf)[tid] = make_uint4(__float_as_uint(h.x), __float_as_uint(h.y),
                                           __float_as_uint(h.z), __float_as_uint(h.w));
    }
}

// ---------------------------------------------------------------------------
// Kernel B: pre = emb @ W_hi^T + b   (M=4096, N=1024, K=1024)
// 64x64 tile, TK=16, 256 threads, 4x4 micro-tile per thread
// ---------------------------------------------------------------------------
#define TM 64
#define TN 64
#define TK 16
#define SPAD 68

__global__ __launch_bounds__(256) void gemm_kernel(const float* __restrict__ Whi,
                                                   const float* __restrict__ b) {
    __shared__ float As[TK][SPAD];
    __shared__ float Bs[TK][SPAD];

    int tid = threadIdx.x;
    int tx  = tid & 15;
    int ty  = tid >> 4;
    int m0  = blockIdx.y * TM;
    int n0  = blockIdx.x * TN;
    int lr  = tid >> 2;
    int lk  = (tid & 3) * 4;

    float acc[4][4] = {};
    const float* A = g_emb;

    for (int k0 = 0; k0 < HID; k0 += TK) {
        float4 av = *(const float4*)(A   + (size_t)(m0 + lr) * HID + k0 + lk);
        float4 bv = *(const float4*)(Whi + (size_t)(n0 + lr) * HID + k0 + lk);
        As[lk+0][lr] = av.x; As[lk+1][lr] = av.y; As[lk+2][lr] = av.z; As[lk+3][lr] = av.w;
        Bs[lk+0][lr] = bv.x; Bs[lk+1][lr] = bv.y; Bs[lk+2][lr] = bv.z; Bs[lk+3][lr] = bv.w;
        __syncthreads();

        #pragma unroll
        for (int kk = 0; kk < TK; kk++) {
            float4 ra = *(const float4*)&As[kk][ty * 4];
            float4 rb = *(const float4*)&Bs[kk][tx * 4];
            float a[4] = {ra.x, ra.y, ra.z, ra.w};
            float c[4] = {rb.x, rb.y, rb.z, rb.w};
            #pragma unroll
            for (int i = 0; i < 4; i++)
                #pragma unroll
                for (int j = 0; j < 4; j++)
                    acc[i][j] += a[i] * c[j];
        }
        __syncthreads();
    }

    #pragma unroll
    for (int j = 0; j < 4; j++) {
        int n = n0 + tx * 4 + j;
        float bj = b[n];
        #pragma unroll
        for (int i = 0; i < 4; i++) {
            int m = m0 + ty * 4 + i;
            g_pre[(size_t)m * HID + n] = acc[i][j] + bj;
        }
    }
}

// ---------------------------------------------------------------------------
// Kernel C: persistent RNN, barrier-free, low-contention.
//   - warp w owns rows r0 = cta*16 + 2w, r1 = r0+1 (weights in 64 regs/lane)
//   - ONLY warp 0 polls h_s (sentinel data-poll, 8 float4 groups per lane),
//     writing arrived groups straight into smem (double-buffered)
//   - one __syncthreads per step; producers publish via plain st.cg
// ---------------------------------------------------------------------------
__global__ __launch_bounds__(RTHR) void rnn_kernel(const float* __restrict__ Whh,
                                                   float* __restrict__ out) {
    __shared__ float hs[2][HID];
    int tid  = threadIdx.x;
    int w    = tid >> 5;
    int lane = tid & 31;
    int r0   = blockIdx.x * 16 + w * 2;
    int r1   = r0 + 1;

    // Two W_hh rows per warp in registers (col = k*32 + lane)
    float wA[32], wB[32];
    #pragma unroll
    for (int k = 0; k < 32; k++) {
        wA[k] = Whh[(size_t)r0 * HID + k * 32 + lane];
        wB[k] = Whh[(size_t)r1 * HID + k * 32 + lane];
    }

    for (int s = 0; s < SEQ; s++) {
        // independent prefetch of this warp's pre values (lane 0 only)
        float p0 = 0.f, p1 = 0.f;
        if (lane == 0) {
            p0 = __ldg(&g_pre[(size_t)s * HID + r0]);
            p1 = __ldg(&g_pre[(size_t)s * HID + r1]);
        }

        float* hb = hs[s & 1];

        // ---- warp 0: poll h_s data (sentinel), fill smem as groups arrive ----
        if (w == 0) {
            const unsigned* base = g_hbuf + (size_t)s * HID;
            unsigned done = 0u;              // 8-group bitmask per lane
            while (done != 0xffu) {
                #pragma unroll
                for (int g = 0; g < 8; g++) {
                    if (!(done & (1u << g))) {
                        const unsigned* p = base + g * 128 + lane * 4;
                        unsigned x0, x1, x2, x3;
                        asm volatile("ld.volatile.global.v4.u32 {%0,%1,%2,%3}, [%4];"
                                     : "=r"(x0), "=r"(x1), "=r"(x2), "=r"(x3)
                                     : "l"(p) : "memory");
                        if (x0 != SENT && x1 != SENT && x2 != SENT && x3 != SENT) {
                            done |= (1u << g);
                            ((float4*)(hb + g * 128 + lane * 4))[0] =
                                make_float4(__uint_as_float(x0), __uint_as_float(x1),
                                            __uint_as_float(x2), __uint_as_float(x3));
                        }
                    }
                }
            }
        }
        __syncthreads();   // h_s complete in smem; prev buffer free (see proof)

        // ---- two dots per warp, sharing each LDS ----
        float a = 0.f, b = 0.f;
        #pragma unroll
        for (int k = 0; k < 32; k++) {
            float hv = hb[k * 32 + lane];
            a += wA[k] * hv;
            b += wB[k] * hv;
        }
        #pragma unroll
        for (int o = 16; o > 0; o >>= 1) {
            a += __shfl_xor_sync(0xffffffffu, a, o);
            b += __shfl_xor_sync(0xffffffffu, b, o);
        }

        if (lane == 0) {
            float h0n = tanhf(a + p0);
            float h1n = tanhf(b + p1);
            size_t o0 = (size_t)(s + 1) * HID + r0;
            __stcg(&out[o0], h0n);
            __stcg(&out[o0 + 1], h1n);
            // publish to comm buffer (word-atomic, value is the flag)
            asm volatile("st.global.cg.u32 [%0], %1;"
                         :: "l"(g_hbuf + o0), "r"(__float_as_uint(h0n)) : "memory");
            asm volatile("st.global.cg.u32 [%0], %1;"
                         :: "l"(g_hbuf + o0 + 1), "r"(__float_as_uint(h1n)) : "memory");
        }
        // no trailing bar: smem is double-buffered; by bar(s) every warp has
        // finished compute(s-1) <= wait: bar(s) is AFTER poll(s); any warp past
        // bar(s) has finished compute(s-2), and buffer parity (s&1) was last
        // read at step s-2 -> safe to overwrite at step s.
    }
}

// ---------------------------------------------------------------------------
extern "C" void kernel_launch(void* const* d_in, const int* in_sizes, int n_in,
                              void* d_out, int out_size) {
    const int*   src = (const int*)  d_in[0];
    const float* W   = (const float*)d_in[1];
    const float* h0  = (const float*)d_in[2];
    const float* Whi = (const float*)d_in[3];
    const float* Whh = (const float*)d_in[4];
    const float* b   = (const float*)d_in[5];
    float* out = (float*)d_out;

    init_kernel<<<256, 256>>>();
    embed_kernel<<<SEQ, 256>>>(src, W, h0, out);

    dim3 gg(HID / TN, SEQ / TM);
    gemm_kernel<<<gg, 256>>>(Whi, b);

    rnn_kernel<<<GRID, RTHR>>>(Whh, out);
}

// round 9
// speedup vs baseline: 1.6059x; 1.6059x over previous
#include <cuda_runtime.h>

#define HID   1024
#define SEQ   4096
#define GRID  128     // persistent CTAs (<= SM count -> co-resident)
#define NTHR  512     // warps 0-7: RNN rows; warps 8-15: GEMM tiles

// Scratch (device globals; no allocation)
__device__ float    g_emb[(size_t)SEQ * HID];   // normalized embeddings
__device__ float    g_pre[(size_t)SEQ * HID];   // W_hi @ x_t + b
__device__ unsigned g_cnt4[4 * SEQ];            // split barrier counters (4 lines)
__device__ unsigned g_pf[16 * 64];              // GEMM tile flags [nb][mb]

// ---------------------------------------------------------------------------
// Kernel A: embedding lookup + L2 normalize; out[0] = h0.
// Also re-zeros this token's 4 barrier counter words and (block 0) tile flags.
// ---------------------------------------------------------------------------
__global__ void embed_kernel(const int* __restrict__ src,
                             const float* __restrict__ W,
                             const float* __restrict__ h0,
                             float* __restrict__ out) {
    int t   = blockIdx.x;
    int tid = threadIdx.x;

    if (tid < 4) g_cnt4[tid * SEQ + t] = 0u;           // reset barrier slot
    if (t == 0 && tid < 256) {                         // reset tile flags
        #pragma unroll
        for (int i = 0; i < 4; i++) g_pf[tid * 4 + i] = 0u;
    }

    const float4* row = (const float4*)(W + (size_t)src[t] * HID);
    float4 v = row[tid];                       // 256 * 4 = 1024 elements
    float  ss = v.x*v.x + v.y*v.y + v.z*v.z + v.w*v.w;

    #pragma unroll
    for (int o = 16; o > 0; o >>= 1)
        ss += __shfl_xor_sync(0xffffffffu, ss, o);

    __shared__ float warp_ss[8];
    __shared__ float s_scale;
    int w = tid >> 5, l = tid & 31;
    if (l == 0) warp_ss[w] = ss;
    __syncthreads();
    if (tid == 0) {
        float tot = 0.f;
        #pragma unroll
        for (int i = 0; i < 8; i++) tot += warp_ss[i];
        float n = fmaxf(sqrtf(tot), 1e-12f);
        s_scale = 1.0f / n;
    }
    __syncthreads();

    float sc = s_scale;
    float4 o4 = make_float4(v.x*sc, v.y*sc, v.z*sc, v.w*sc);
    ((float4*)g_emb)[(size_t)t * (HID/4) + tid] = o4;

    if (t == 0)   // out row 0 = h0
        ((float4*)out)[tid] = ((const float4*)h0)[tid];
}

// ---------------------------------------------------------------------------
// Fused persistent kernel.
//   Warps 8-15 (gtid 0..255): GEMM pre = emb @ W_hi^T + b, 8 tiles of 64x64
//     (CTA c: n-block nb = c>>3 fixed, m-blocks mb = (c&7)*8 + j, j=0..7),
//     flag g_pf[nb*64+mb] via st.release after each tile. Named barrier 2.
//   Warps 0-7: RNN, one row per warp (row = cta*8 + w), W_hh row in 32 regs.
//     Grid barrier per step: bar -> tid0 red.release.gpu on g_cnt4[cta&3][s]
//     -> tid0 polls 4 words (volatile, pipelined) + fence.acq_rel. Named bar 1.
// ---------------------------------------------------------------------------
#define TK   16
#define SPAD 68

__global__ __launch_bounds__(NTHR) void fused_kernel(const float* __restrict__ Whh,
                                                     const float* __restrict__ Whi,
                                                     const float* __restrict__ b,
                                                     float* __restrict__ out) {
    __shared__ float hs[HID];
    __shared__ float As[TK][SPAD];
    __shared__ float Bs[TK][SPAD];

    int tid  = threadIdx.x;
    int w    = tid >> 5;
    int lane = tid & 31;
    int cta  = blockIdx.x;

    if (w >= 8) {
        // ================= GEMM warp group (gtid 0..255) =================
        int gtid = tid - 256;
        int tx  = gtid & 15;
        int ty  = gtid >> 4;
        int lr  = gtid >> 2;
        int lk  = (gtid & 3) * 4;
        int nb  = cta >> 3;
        int n0  = nb * 64;

        for (int j = 0; j < 8; j++) {
            int mb = (cta & 7) * 8 + j;
            int m0 = mb * 64;

            float acc[4][4] = {};
            for (int k0 = 0; k0 < HID; k0 += TK) {
                float4 av = *(const float4*)(g_emb + (size_t)(m0 + lr) * HID + k0 + lk);
                float4 bv = *(const float4*)(Whi   + (size_t)(n0 + lr) * HID + k0 + lk);
                As[lk+0][lr] = av.x; As[lk+1][lr] = av.y; As[lk+2][lr] = av.z; As[lk+3][lr] = av.w;
                Bs[lk+0][lr] = bv.x; Bs[lk+1][lr] = bv.y; Bs[lk+2][lr] = bv.z; Bs[lk+3][lr] = bv.w;
                asm volatile("bar.sync 2, 256;" ::: "memory");

                #pragma unroll
                for (int kk = 0; kk < TK; kk++) {
                    float4 ra = *(const float4*)&As[kk][ty * 4];
                    float4 rb = *(const float4*)&Bs[kk][tx * 4];
                    float a[4] = {ra.x, ra.y, ra.z, ra.w};
                    float c[4] = {rb.x, rb.y, rb.z, rb.w};
                    #pragma unroll
                    for (int i = 0; i < 4; i++)
                        #pragma unroll
                        for (int jj = 0; jj < 4; jj++)
                            acc[i][jj] += a[i] * c[jj];
                }
                asm volatile("bar.sync 2, 256;" ::: "memory");
            }

            #pragma unroll
            for (int jj = 0; jj < 4; jj++) {
                int n = n0 + tx * 4 + jj;
                float bj = b[n];
                #pragma unroll
                for (int i = 0; i < 4; i++) {
                    int m = m0 + ty * 4 + i;
                    float v = acc[i][jj] + bj;          // FIX: bias was dropped in R8
                    asm volatile("st.global.cg.f32 [%0], %1;"
                                 :: "l"(g_pre + (size_t)m * HID + n),
                                    "f"(v) : "memory");
                }
            }
            asm volatile("bar.sync 2, 256;" ::: "memory");   // stores issued CTA-wide
            if (gtid == 0)
                asm volatile("st.release.gpu.global.u32 [%0], %1;"
                             :: "l"(g_pf + nb * 64 + mb), "r"(1u) : "memory");
        }
        return;   // GEMM warps exit; named barrier 1 unaffected
    }

    // ==================== RNN warp group (tid 0..255) ====================
    int row = cta * 8 + w;
    int nbc = cta >> 3;           // n-block containing this CTA's rows

    // This warp's W_hh row in registers (col = k*32 + lane)
    float wreg[32];
    #pragma unroll
    for (int k = 0; k < 32; k++)
        wreg[k] = Whh[(size_t)row * HID + k * 32 + lane];

    int mb_ready = -1;

    for (int s = 0; s < SEQ; s++) {
        // ---- lane 0: gate on pre-tile flag (rare), prefetch pre value ----
        float preval = 0.f;
        if (lane == 0) {
            int mb = s >> 6;
            if (mb != mb_ready) {
                const unsigned* fp = g_pf + nbc * 64 + mb;
                unsigned f;
                while (true) {
                    asm volatile("ld.acquire.gpu.global.u32 %0, [%1];"
                                 : "=r"(f) : "l"(fp) : "memory");
                    if (f) break;
                    __nanosleep(128);
                }
                mb_ready = mb;
            }
            asm volatile("ld.global.cg.f32 %0, [%1];"
                         : "=f"(preval) : "l"(g_pre + (size_t)s * HID + row));
        }

        // ---- wait for h_s (grid barrier on slot s-1) ----
        if (s > 0) {
            if (tid == 0) {
                const unsigned* c0 = g_cnt4 + (s - 1);
                unsigned x0, x1, x2, x3;
                do {
                    asm volatile("ld.volatile.global.u32 %0, [%1];" : "=r"(x0) : "l"(c0)           : "memory");
                    asm volatile("ld.volatile.global.u32 %0, [%1];" : "=r"(x1) : "l"(c0 + SEQ)     : "memory");
                    asm volatile("ld.volatile.global.u32 %0, [%1];" : "=r"(x2) : "l"(c0 + 2 * SEQ) : "memory");
                    asm volatile("ld.volatile.global.u32 %0, [%1];" : "=r"(x3) : "l"(c0 + 3 * SEQ) : "memory");
                } while (x0 + x1 + x2 + x3 < GRID);
                asm volatile("fence.acq_rel.gpu;" ::: "memory");
            }
            asm volatile("bar.sync 1, 256;" ::: "memory");   // bar A
        }

        // ---- cooperative fill of h_s into smem (L2-only loads) ----
        float4 hv = __ldcg((const float4*)(out + (size_t)s * HID) + tid);
        ((float4*)hs)[tid] = hv;
        asm volatile("bar.sync 1, 256;" ::: "memory");       // bar B

        // ---- dot(W_hh[row,:], h) ----
        float a0 = 0.f, a1 = 0.f, a2 = 0.f, a3 = 0.f;
        #pragma unroll
        for (int k = 0; k < 32; k += 4) {
            a0 += wreg[k+0] * hs[(k+0)*32 + lane];
            a1 += wreg[k+1] * hs[(k+1)*32 + lane];
            a2 += wreg[k+2] * hs[(k+2)*32 + lane];
            a3 += wreg[k+3] * hs[(k+3)*32 + lane];
        }
        float acc = (a0 + a1) + (a2 + a3);
        #pragma unroll
        for (int o = 16; o > 0; o >>= 1)
            acc += __shfl_xor_sync(0xffffffffu, acc, o);

        if (lane == 0) {
            float hn = tanhf(acc + preval);
            __stcg(&out[(size_t)(s + 1) * HID + row], hn);
        }
        asm volatile("bar.sync 1, 256;" ::: "memory");       // bar C

        if (tid == 0)   // release-arrive: cumulativity covers all CTA stores
            asm volatile("red.release.gpu.global.add.u32 [%0], %1;"
                         :: "l"(g_cnt4 + (cta & 3) * SEQ + s), "r"(1u) : "memory");
    }
}

// ---------------------------------------------------------------------------
extern "C" void kernel_launch(void* const* d_in, const int* in_sizes, int n_in,
                              void* d_out, int out_size) {
    const int*   src = (const int*)  d_in[0];
    const float* W   = (const float*)d_in[1];
    const float* h0  = (const float*)d_in[2];
    const float* Whi = (const float*)d_in[3];
    const float* Whh = (const float*)d_in[4];
    const float* b   = (const float*)d_in[5];
    float* out = (float*)d_out;

    embed_kernel<<<SEQ, 256>>>(src, W, h0, out);
    fused_kernel<<<GRID, NTHR>>>(Whh, Whi, b, out);
}

// round 10
// speedup vs baseline: 2.0335x; 1.2663x over previous
#include <cuda_runtime.h>

#define HID   1024
#define SEQ   4096
#define GRID  32      // RNN persistent CTAs: 4x fewer sync agents than R2
#define RTHR  256     // 8 warps x 4 rows = 32 rows per CTA

// Scratch (device globals; no allocation)
__device__ float    g_emb[(size_t)SEQ * HID];   // normalized embeddings
__device__ float    g_pre[(size_t)SEQ * HID];   // W_hi @ x_t + b
__device__ unsigned g_cnt[SEQ];                 // per-step barrier counters

// ---------------------------------------------------------------------------
// Kernel A: embedding lookup + L2 normalize; zero barrier counters; out[0]=h0
// ---------------------------------------------------------------------------
__global__ void embed_kernel(const int* __restrict__ src,
                             const float* __restrict__ W,
                             const float* __restrict__ h0,
                             float* __restrict__ out) {
    int t   = blockIdx.x;
    int tid = threadIdx.x;

    if (tid == 0) g_cnt[t] = 0u;               // reset barrier slot every replay

    const float4* row = (const float4*)(W + (size_t)src[t] * HID);
    float4 v = row[tid];                       // 256 * 4 = 1024 elements
    float  ss = v.x*v.x + v.y*v.y + v.z*v.z + v.w*v.w;

    #pragma unroll
    for (int o = 16; o > 0; o >>= 1)
        ss += __shfl_xor_sync(0xffffffffu, ss, o);

    __shared__ float warp_ss[8];
    __shared__ float s_scale;
    int w = tid >> 5, l = tid & 31;
    if (l == 0) warp_ss[w] = ss;
    __syncthreads();
    if (tid == 0) {
        float tot = 0.f;
        #pragma unroll
        for (int i = 0; i < 8; i++) tot += warp_ss[i];
        float n = fmaxf(sqrtf(tot), 1e-12f);
        s_scale = 1.0f / n;
    }
    __syncthreads();

    float sc = s_scale;
    float4 o4 = make_float4(v.x*sc, v.y*sc, v.z*sc, v.w*sc);
    ((float4*)g_emb)[(size_t)t * (HID/4) + tid] = o4;

    if (t == 0)   // out row 0 = h0
        ((float4*)out)[tid] = ((const float4*)h0)[tid];
}

// ---------------------------------------------------------------------------
// Kernel B: pre = emb @ W_hi^T + b   (M=4096, N=1024, K=1024)  [R2-proven]
// ---------------------------------------------------------------------------
#define TM 64
#define TN 64
#define TK 16
#define SPAD 68

__global__ __launch_bounds__(256) void gemm_kernel(const float* __restrict__ Whi,
                                                   const float* __restrict__ b) {
    __shared__ float As[TK][SPAD];
    __shared__ float Bs[TK][SPAD];

    int tid = threadIdx.x;
    int tx  = tid & 15;
    int ty  = tid >> 4;
    int m0  = blockIdx.y * TM;
    int n0  = blockIdx.x * TN;
    int lr  = tid >> 2;
    int lk  = (tid & 3) * 4;

    float acc[4][4] = {};
    const float* A = g_emb;

    for (int k0 = 0; k0 < HID; k0 += TK) {
        float4 av = *(const float4*)(A   + (size_t)(m0 + lr) * HID + k0 + lk);
        float4 bv = *(const float4*)(Whi + (size_t)(n0 + lr) * HID + k0 + lk);
        As[lk+0][lr] = av.x; As[lk+1][lr] = av.y; As[lk+2][lr] = av.z; As[lk+3][lr] = av.w;
        Bs[lk+0][lr] = bv.x; Bs[lk+1][lr] = bv.y; Bs[lk+2][lr] = bv.z; Bs[lk+3][lr] = bv.w;
        __syncthreads();

        #pragma unroll
        for (int kk = 0; kk < TK; kk++) {
            float4 ra = *(const float4*)&As[kk][ty * 4];
            float4 rb = *(const float4*)&Bs[kk][tx * 4];
            float a[4] = {ra.x, ra.y, ra.z, ra.w};
            float c[4] = {rb.x, rb.y, rb.z, rb.w};
            #pragma unroll
            for (int i = 0; i < 4; i++)
                #pragma unroll
                for (int j = 0; j < 4; j++)
                    acc[i][j] += a[i] * c[j];
        }
        __syncthreads();
    }

    #pragma unroll
    for (int j = 0; j < 4; j++) {
        int n = n0 + tx * 4 + j;
        float bj = b[n];
        #pragma unroll
        for (int i = 0; i < 4; i++) {
            int m = m0 + ty * 4 + i;
            g_pre[(size_t)m * HID + n] = acc[i][j] + bj;
        }
    }
}

// ---------------------------------------------------------------------------
// Kernel C: persistent RNN, 32 CTAs. Warp w owns 4 contiguous rows
// base = cta*32 + w*4; their W_hh slices live in 128 regs/lane.
// Grid barrier: bar -> tid0 red.release.gpu.add g_cnt[s];
// wait: tid0 ld.acquire.gpu poll on g_cnt[s-1] (single word, 32 agents).
// ---------------------------------------------------------------------------
__global__ __launch_bounds__(RTHR) void rnn_kernel(const float* __restrict__ Whh,
                                                   float* __restrict__ out) {
    __shared__ float hs[HID];
    int tid  = threadIdx.x;
    int w    = tid >> 5;
    int lane = tid & 31;
    int cta  = blockIdx.x;
    int base = cta * 32 + w * 4;    // 4 contiguous rows per warp

    // 4 W_hh rows per warp in registers (col = k*32 + lane)
    float wreg[4][32];
    #pragma unroll
    for (int i = 0; i < 4; i++)
        #pragma unroll
        for (int k = 0; k < 32; k++)
            wreg[i][k] = Whh[(size_t)(base + i) * HID + k * 32 + lane];

    for (int s = 0; s < SEQ; s++) {
        // prefetch this warp's 4 pre values (lane 0, contiguous float4)
        float4 pv = make_float4(0.f, 0.f, 0.f, 0.f);
        if (lane == 0)
            pv = __ldcg((const float4*)(g_pre + (size_t)s * HID + base));

        // ---- wait for h_s (single-word acquire poll, R2 style) ----
        if (s > 0) {
            if (tid == 0) {
                unsigned v;
                do {
                    asm volatile("ld.acquire.gpu.global.u32 %0, [%1];"
                                 : "=r"(v) : "l"(g_cnt + (s - 1)) : "memory");
                } while (v < GRID);
            }
            __syncthreads();                      // bar A: h_s globally ready
        }

        // ---- cooperative fill of h_s into smem (L2-only loads) ----
        float4 hv = __ldcg((const float4*)(out + (size_t)s * HID) + tid);
        ((float4*)hs)[tid] = hv;
        __syncthreads();                          // bar B

        // ---- 4 dots per warp, sharing each LDS across rows ----
        float a0 = 0.f, a1 = 0.f, a2 = 0.f, a3 = 0.f;
        #pragma unroll
        for (int k = 0; k < 32; k++) {
            float h = hs[k * 32 + lane];
            a0 += wreg[0][k] * h;
            a1 += wreg[1][k] * h;
            a2 += wreg[2][k] * h;
            a3 += wreg[3][k] * h;
        }
        #pragma unroll
        for (int o = 16; o > 0; o >>= 1) {
            a0 += __shfl_xor_sync(0xffffffffu, a0, o);
            a1 += __shfl_xor_sync(0xffffffffu, a1, o);
            a2 += __shfl_xor_sync(0xffffffffu, a2, o);
            a3 += __shfl_xor_sync(0xffffffffu, a3, o);
        }

        if (lane == 0) {
            float4 hn = make_float4(tanhf(a0 + pv.x), tanhf(a1 + pv.y),
                                    tanhf(a2 + pv.z), tanhf(a3 + pv.w));
            __stcg((float4*)(out + (size_t)(s + 1) * HID + base), hn);
        }
        __syncthreads();                          // bar C: all rows stored

        if (tid == 0)   // release-arrive: orders the CTA's h stores
            asm volatile("red.release.gpu.global.add.u32 [%0], %1;"
                         :: "l"(g_cnt + s), "r"(1u) : "memory");
    }
}

// ---------------------------------------------------------------------------
extern "C" void kernel_launch(void* const* d_in, const int* in_sizes, int n_in,
                              void* d_out, int out_size) {
    const int*   src = (const int*)  d_in[0];
    const float* W   = (const float*)d_in[1];
    const float* h0  = (const float*)d_in[2];
    const float* Whi = (const float*)d_in[3];
    const float* Whh = (const float*)d_in[4];
    const float* b   = (const float*)d_in[5];
    float* out = (float*)d_out;

    embed_kernel<<<SEQ, 256>>>(src, W, h0, out);

    dim3 gg(HID / TN, SEQ / TM);
    gemm_kernel<<<gg, 256>>>(Whi, b);

    rnn_kernel<<<GRID, RTHR>>>(Whh, out);
}